// round 3
// baseline (speedup 1.0000x reference)
#include <cuda_runtime.h>
#include <cuda_bf16.h>
#include <cstdint>

#define NUM_KEYS 64
#define THREADS 256
#define VEC_PER_THREAD 8   // 8 x int4 = 32 elements = 128B loaded + 128B stored per thread

// out[i] = b[in[i] & 63]  (bench inputs are randint(0,64), always in range;
// the &63 keeps shared reads in-bounds for any input).
__global__ void __launch_bounds__(THREADS) lut_gather_kernel(
    const int4* __restrict__ in4,
    const float* __restrict__ b,
    float4* __restrict__ out4,
    int n4)
{
    __shared__ float lut[NUM_KEYS];
    if (threadIdx.x < NUM_KEYS) {
        lut[threadIdx.x] = b[threadIdx.x];
    }
    __syncthreads();

    const int block_base = blockIdx.x * (THREADS * VEC_PER_THREAD);
    const bool full = (block_base + THREADS * VEC_PER_THREAD) <= n4;  // uniform per block

    if (full) {
        int4 v[VEC_PER_THREAD];
        // Front-batched independent LDG.128 (MLP=8), fully coalesced.
        #pragma unroll
        for (int j = 0; j < VEC_PER_THREAD; j++) {
            v[j] = in4[block_base + j * THREADS + threadIdx.x];
        }
        #pragma unroll
        for (int j = 0; j < VEC_PER_THREAD; j++) {
            float4 o;
            o.x = lut[v[j].x & (NUM_KEYS - 1)];
            o.y = lut[v[j].y & (NUM_KEYS - 1)];
            o.z = lut[v[j].z & (NUM_KEYS - 1)];
            o.w = lut[v[j].w & (NUM_KEYS - 1)];
            out4[block_base + j * THREADS + threadIdx.x] = o;
        }
    } else {
        #pragma unroll
        for (int j = 0; j < VEC_PER_THREAD; j++) {
            int idx = block_base + j * THREADS + threadIdx.x;
            if (idx < n4) {
                int4 v = in4[idx];
                float4 o;
                o.x = lut[v.x & (NUM_KEYS - 1)];
                o.y = lut[v.y & (NUM_KEYS - 1)];
                o.z = lut[v.z & (NUM_KEYS - 1)];
                o.w = lut[v.w & (NUM_KEYS - 1)];
                out4[idx] = o;
            }
        }
    }
}

extern "C" void kernel_launch(void* const* d_in, const int* in_sizes, int n_in,
                              void* d_out, int out_size) {
    // metadata order: inputs (int32, 8*4096*1024), b (float32, 64), keys (float32, 64)
    const int*   in  = (const int*)d_in[0];
    const float* b   = (const float*)d_in[1];
    float*       out = (float*)d_out;

    int n  = in_sizes[0];          // 33,554,432
    int n4 = n >> 2;               // 8,388,608 int4 elements

    const int per_block = THREADS * VEC_PER_THREAD;      // 2048 int4 per block
    int blocks = (n4 + per_block - 1) / per_block;        // 4096 for the bench shape

    lut_gather_kernel<<<blocks, THREADS>>>(
        (const int4*)in, b, (float4*)out, n4);
}